// round 15
// baseline (speedup 1.0000x reference)
#include <cuda_runtime.h>
#include <cuda_fp16.h>
#include <math.h>
#include <stdint.h>

#define NB    8
#define C     192
#define C2    384
#define C4    768
#define HEADS 4
#define HD    48
#define HW    128
#define NPIX  16384
#define GK    192
#define ASEG  8
#define ASEGLEN (NPIX/ASEG)
#define NTILE 64

// ---------------- scratch (static device memory) ----------------
__device__ float g_cps[NB*NTILE*C];
__device__ float g_cpm[NB*NTILE*C];
__device__ float g_cg [NB*C];
__device__ float g_sp [NB*2*NPIX];
__device__ float g_sg [NB*NPIX];
__device__ __half g_wq [NB*C4*GK];
__device__ __half g_wp [C*GK];
__device__ __half g_qkv[(size_t)NB*C4*NPIX];
__device__ __half g_dw [(size_t)NB*C4*NPIX];
__device__ float g_inq [NB*C];
__device__ float g_ink [NB*C];
__device__ float g_spart[(size_t)NB*HEADS*ASEG*HD*HD];
__device__ float g_attn [(size_t)NB*HEADS*HD*HD];

__device__ __forceinline__ float sigmoidf_(float x){ return 1.f/(1.f+expf(-x)); }

__device__ __forceinline__ uint32_t su32(const void* p){
    uint32_t a;
    asm("{ .reg .u64 t; cvta.to.shared.u64 t, %1; cvt.u32.u64 %0, t; }" : "=r"(a) : "l"(p));
    return a;
}
#define CP16(dst, src) \
    asm volatile("cp.async.cg.shared.global [%0], [%1], 16;" :: "r"(dst), "l"(src))

__device__ __forceinline__ void ldm_x4(uint32_t* r, uint32_t addr){
    asm volatile("ldmatrix.sync.aligned.m8n8.x4.shared.b16 {%0,%1,%2,%3}, [%4];"
      : "=r"(r[0]),"=r"(r[1]),"=r"(r[2]),"=r"(r[3]) : "r"(addr));
}
__device__ __forceinline__ void ldm_x2(uint32_t* r, uint32_t addr){
    asm volatile("ldmatrix.sync.aligned.m8n8.x2.shared.b16 {%0,%1}, [%2];"
      : "=r"(r[0]),"=r"(r[1]) : "r"(addr));
}
__device__ __forceinline__ void ldm_x2t(uint32_t* r, uint32_t addr){
    asm volatile("ldmatrix.sync.aligned.m8n8.x2.trans.shared.b16 {%0,%1}, [%2];"
      : "=r"(r[0]),"=r"(r[1]) : "r"(addr));
}
__device__ __forceinline__ void mma16816f(float* c, uint32_t a0, uint32_t a1,
                                          uint32_t a2, uint32_t a3,
                                          uint32_t b0, uint32_t b1){
    asm volatile(
      "mma.sync.aligned.m16n8k16.row.col.f32.f16.f16.f32 "
      "{%0,%1,%2,%3},{%4,%5,%6,%7},{%8,%9},{%0,%1,%2,%3};"
      : "+f"(c[0]), "+f"(c[1]), "+f"(c[2]), "+f"(c[3])
      : "r"(a0), "r"(a1), "r"(a2), "r"(a3), "r"(b0), "r"(b1));
}

// ---------------- K1: one pass over x -> channel + pixel stats ----------------
__global__ __launch_bounds__(256)
void k_stats(const float* __restrict__ x){
    __shared__ float sps[8*256], spm[8*256];
    int tile = blockIdx.x, b = blockIdx.y;
    int tid = threadIdx.x, w = tid>>5, lane = tid&31;
    int p0 = tile*256;
    float ps[8], pm[8];
    #pragma unroll
    for (int i=0;i<8;i++){ ps[i]=0.f; pm[i]=-1e30f; }
    for (int ci=0; ci<24; ci++){
        int c = w*24 + ci;
        const float* row = x + ((size_t)b*C + c)*NPIX + p0;
        float cs = 0.f, cm = -1e30f;
        #pragma unroll
        for (int it=0; it<8; it++){
            float v = row[it*32 + lane];
            ps[it] += v; pm[it] = fmaxf(pm[it], v);
            cs += v;     cm = fmaxf(cm, v);
        }
        #pragma unroll
        for (int o=16;o;o>>=1){
            cs += __shfl_xor_sync(~0u, cs, o);
            cm = fmaxf(cm, __shfl_xor_sync(~0u, cm, o));
        }
        if (lane==0){
            g_cps[(b*NTILE + tile)*C + c] = cs;
            g_cpm[(b*NTILE + tile)*C + c] = cm;
        }
    }
    #pragma unroll
    for (int it=0; it<8; it++){
        sps[w*256 + it*32 + lane] = ps[it];
        spm[w*256 + it*32 + lane] = pm[it];
    }
    __syncthreads();
    if (tid < 256){
        int p = tid;
        float s = 0.f, m = -1e30f;
        #pragma unroll
        for (int ww=0; ww<8; ww++){
            s += sps[ww*256+p];
            m = fmaxf(m, spm[ww*256+p]);
        }
        g_sp[(size_t)b*2*NPIX + p0 + p]        = s*(1.f/C);
        g_sp[(size_t)b*2*NPIX + NPIX + p0 + p] = m;
    }
}

// ---------------- K2: SE channel gate MLP ----------------
__global__ void k_chan_gate(const float* __restrict__ w1, const float* __restrict__ w2){
    int b = blockIdx.x, t = threadIdx.x;
    __shared__ float pool[C2], sq[48];
    {
        float s = 0.f, m = -1e30f;
        for (int tile=0; tile<NTILE; tile++){
            s += g_cps[(b*NTILE + tile)*C + t];
            m = fmaxf(m, g_cpm[(b*NTILE + tile)*C + t]);
        }
        pool[t]   = s*(1.f/NPIX);
        pool[C+t] = m;
    }
    __syncthreads();
    if (t < 48){
        float a = 0.f;
        #pragma unroll 8
        for (int c=0;c<C2;c++) a += w1[t*C2+c]*pool[c];
        sq[t] = fmaxf(a, 0.f);
    }
    __syncthreads();
    float a = 0.f;
    #pragma unroll
    for (int s=0;s<48;s++) a += w2[t*48+s]*sq[s];
    g_cg[b*C+t] = sigmoidf_(a);
}

// ---------------- K3: 7x7 spatial conv + sigmoid ----------------
__global__ void k_spatial_conv(const float* __restrict__ ws){
    int idx = blockIdx.x*256 + threadIdx.x;
    int b = idx >> 14, p = idx & (NPIX-1);
    int y = p >> 7, xx = p & 127;
    float acc = 0.f;
    #pragma unroll
    for (int ch=0; ch<2; ch++){
        const float* base = g_sp + (size_t)b*2*NPIX + (size_t)ch*NPIX;
        #pragma unroll
        for (int dy=-3; dy<=3; dy++){
            int yy = y+dy;
            if ((unsigned)yy < 128u){
                const float* row = base + yy*HW;
                #pragma unroll
                for (int dx=-3; dx<=3; dx++){
                    int xc = xx+dx;
                    if ((unsigned)xc < 128u)
                        acc += row[xc]*__ldg(&ws[ch*49 + (dy+3)*7 + (dx+3)]);
                }
            }
        }
    }
    g_sg[(size_t)b*NPIX + p] = sigmoidf_(acc);
}

// ---------------- weight conversions ----------------
__global__ void k_wcvt(const float* __restrict__ w, __half* __restrict__ oh){
    size_t i = ((size_t)blockIdx.x*256 + threadIdx.x)*4;
    int b  = (int)(i/(C4*GK));
    int rc = (int)(i - (size_t)b*C4*GK);
    int col = rc % GK;
    float4 v = *(const float4*)(w+rc);
    const float* g = g_cg + b*C;
    v.x *= g[col]; v.y *= g[col+1]; v.z *= g[col+2]; v.w *= g[col+3];
    __half2 a = __floats2half2_rn(v.x, v.y);
    __half2 bb = __floats2half2_rn(v.z, v.w);
    *(uint2*)(oh+i) = make_uint2(*(uint32_t*)&a, *(uint32_t*)&bb);
}

__global__ void k_pcvt(const float* __restrict__ w, __half* __restrict__ oh){
    size_t i = ((size_t)blockIdx.x*256 + threadIdx.x)*4;
    float4 v = *(const float4*)(w+i);
    __half2 a = __floats2half2_rn(v.x, v.y);
    __half2 b = __floats2half2_rn(v.z, v.w);
    *(uint2*)(oh+i) = make_uint2(*(uint32_t*)&a, *(uint32_t*)&b);
}

// ================= qkv GEMM: fp32-B staged+converted, A ping-pong cp.async =================
#define S_A6 0
#define A6SZ 25600
#define S_B6 51200
#define SMEM6 103424

__global__ __launch_bounds__(256)
void k_hmma6(const __half* __restrict__ Ag, long sA,
             const float* __restrict__ Bg,
             __half* __restrict__ outp, long sC,
             const float* __restrict__ S, int M, int Mtiles){
    extern __shared__ __align__(16) char smem[];
    uint32_t sb = su32(smem);
    int b = blockIdx.x & 7, bn = (blockIdx.x >> 3)*128;
    const __half* A = Ag + (size_t)b*sA;
    const float* B = Bg + (size_t)b*C*NPIX;
    const float* Sp = S + (size_t)b*NPIX;

    int tid = threadIdx.x, wid = tid>>5, lane = tid&31;
    int wr = wid>>2, wc = wid&3;
    int gi = lane>>2, li4 = lane&3;

    for (int e=tid; e<1536; e+=256){
        int r = e/24, ch = e - (e/24)*24;
        CP16(sb + S_A6 + r*400 + ch*16, (const char*)(A + (size_t)r*GK) + ch*16);
    }
    asm volatile("cp.async.commit_group;" ::: "memory");

    for (int e=tid; e<6144; e+=256){
        int k = e>>5, c4 = e&31;
        float4 v = *(const float4*)(B + (size_t)k*NPIX + bn + c4*4);
        __half2 h0 = __floats2half2_rn(v.x, v.y);
        __half2 h1 = __floats2half2_rn(v.z, v.w);
        *(uint2*)(smem + S_B6 + k*272 + c4*8) = make_uint2(*(uint32_t*)&h0, *(uint32_t*)&h1);
    }

    uint32_t aBase = sb + S_A6 + ((wr*32 + (lane&15))*400) + (lane>>4)*16;
    uint32_t bA    = sb + S_B6 + (lane&15)*272 + wc*64;

    for (int ot=0; ot<Mtiles; ot++){
        if (ot+1 < Mtiles){
            int bm1 = (ot+1)*64;
            uint32_t dstb = sb + S_A6 + ((ot+1)&1)*A6SZ;
            for (int e=tid; e<1536; e+=256){
                int r = e/24, ch = e - (e/24)*24;
                CP16(dstb + r*400 + ch*16, (const char*)(A + (size_t)(bm1+r)*GK) + ch*16);
            }
            asm volatile("cp.async.commit_group;" ::: "memory");
            asm volatile("cp.async.wait_group 1;" ::: "memory");
        } else {
            asm volatile("cp.async.wait_group 0;" ::: "memory");
        }
        __syncthreads();

        uint32_t aA = aBase + (ot&1)*A6SZ;
        float acc[2][4][4];
        #pragma unroll
        for (int i=0;i<2;i++)
            #pragma unroll
            for (int j=0;j<4;j++)
                #pragma unroll
                for (int r=0;r<4;r++) acc[i][j][r]=0.f;

        #pragma unroll
        for (int ks=0; ks<12; ks++){
            uint32_t Af[2][4], Bf[4][2];
            #pragma unroll
            for (int mi=0; mi<2; mi++) ldm_x4(Af[mi], aA + mi*6400 + ks*32);
            #pragma unroll
            for (int ni=0; ni<4; ni++) ldm_x2t(Bf[ni], bA + ks*4352 + ni*16);
            #pragma unroll
            for (int mi=0; mi<2; mi++)
                #pragma unroll
                for (int ni=0; ni<4; ni++)
                    mma16816f(acc[mi][ni], Af[mi][0],Af[mi][1],Af[mi][2],Af[mi][3],
                              Bf[ni][0],Bf[ni][1]);
        }

        int bm = ot*64;
        __half* O = outp + (size_t)b*sC;
        #pragma unroll
        for (int ni=0; ni<4; ni++){
            int n = bn + wc*32 + ni*8 + li4*2;
            float2 sv = *(const float2*)&Sp[n];
            #pragma unroll
            for (int mi=0; mi<2; mi++){
                int m0 = bm + wr*32 + mi*16 + gi;
                *(__half2*)(O + (size_t)m0*NPIX + n) =
                    __floats2half2_rn(acc[mi][ni][0]*sv.x, acc[mi][ni][1]*sv.y);
                *(__half2*)(O + (size_t)(m0+8)*NPIX + n) =
                    __floats2half2_rn(acc[mi][ni][2]*sv.x, acc[mi][ni][3]*sv.y);
            }
        }
        __syncthreads();
    }
}

// ---------------- depthwise 3x3 over a channel GROUP (0: q,k + norms; 1: gate,v) ----------------
#define DWP 144
__global__ __launch_bounds__(256)
void k_dw2(const float* __restrict__ wd, int group){
    __shared__ __half img[128*DWP];
    __shared__ float wsum[8];
    int b    = blockIdx.x / C2;        // 384 channel-slots per batch
    int cidx = blockIdx.x - b*C2;
    int ch;
    if (group == 0) ch = (cidx < C) ? cidx       : 2*C + (cidx - C);   // q, k
    else            ch = (cidx < C) ? C + cidx   : 3*C + (cidx - C);   // gate, v
    int bc = b*C4 + ch;
    int tid = threadIdx.x;
    const __half* in = g_qkv + (size_t)bc*NPIX;

    float w[9];
    #pragma unroll
    for (int k=0;k<9;k++) w[k] = __ldg(&wd[ch*9+k]);

    for (int r=tid; r<128; r+=256){
        *(uint4*)&img[r*DWP]       = make_uint4(0,0,0,0);
        *(uint4*)&img[r*DWP + 136] = make_uint4(0,0,0,0);
    }
    for (int i=tid; i<2048; i+=256){
        int r = i>>4, c = i&15;
        *(uint4*)&img[r*DWP + 8 + c*8] = ((const uint4*)in)[i];
    }
    __syncthreads();

    __half* op = g_dw + (size_t)bc*NPIX;
    float ssq = 0.f;
    #pragma unroll
    for (int it=0; it<8; it++){
        int idx = it*256 + tid;
        int r  = idx>>4;
        int x0 = (idx&15)*8;
        float acc[8] = {0.f,0.f,0.f,0.f,0.f,0.f,0.f,0.f};
        #pragma unroll
        for (int dr=-1; dr<=1; dr++){
            int rr = r + dr;
            if ((unsigned)rr < 128u){
                const __half* rp = &img[rr*DWP + x0 + 6];
                float f[12];
                #pragma unroll
                for (int j=0;j<6;j++){
                    float2 p = __half22float2(*(const __half2*)(rp + 2*j));
                    f[2*j] = p.x; f[2*j+1] = p.y;
                }
                float w0 = w[(dr+1)*3], w1 = w[(dr+1)*3+1], w2 = w[(dr+1)*3+2];
                #pragma unroll
                for (int u=0;u<8;u++)
                    acc[u] += w0*f[u+1] + w1*f[u+2] + w2*f[u+3];
            }
        }
        __align__(16) __half hv[8];
        #pragma unroll
        for (int u=0;u<8;u++){ hv[u] = __float2half(acc[u]); ssq += acc[u]*acc[u]; }
        ((uint4*)op)[idx] = *(uint4*)hv;
    }

    if (group == 0){
        #pragma unroll
        for (int o=16;o;o>>=1) ssq += __shfl_xor_sync(~0u, ssq, o);
        if ((tid&31)==0) wsum[tid>>5] = ssq;
        __syncthreads();
        if (tid==0){
            float s = 0.f;
            #pragma unroll
            for (int i=0;i<8;i++) s += wsum[i];
            float inv = 1.f/fmaxf(sqrtf(s), 1e-12f);
            if (cidx < C) g_inq[b*C + cidx]     = inv;
            else          g_ink[b*C + cidx - C] = inv;
        }
    }
}

// ---------------- q.k^T partials on tensor cores ----------------
__global__ __launch_bounds__(256)
void k_attn_mma(){
    __shared__ __half qs[48*72];
    __shared__ __half ks[48*72];
    int bh = blockIdx.x, seg = blockIdx.y;
    int b = bh>>2, hh = bh&3;
    const __half* qb = g_dw + ((size_t)b*C4 + hh*HD)*NPIX + seg*ASEGLEN;
    const __half* kb = g_dw + ((size_t)b*C4 + 2*C + hh*HD)*NPIX + seg*ASEGLEN;
    int tid = threadIdx.x, wid = tid>>5, lane = tid&31;
    uint32_t qsb = su32(qs), ksb = su32(ks);
    int n0 = wid*8;

    float acc[3][4];
    #pragma unroll
    for (int mi=0;mi<3;mi++)
        #pragma unroll
        for (int r=0;r<4;r++) acc[mi][r]=0.f;

    uint32_t aAddr = qsb + ((lane&15)*72 + (lane>>4)*8)*2;
    uint32_t bAddr = ksb + (((n0 + (lane&7))*72) + (((lane>>3)&1)*8))*2;

    for (int ck=0; ck<ASEGLEN/64; ck++){
        for (int e=tid; e<768; e+=256){
            int which = e>=384;
            int idx = e - which*384;
            int r = idx>>3, c8 = idx&7;
            const __half* src = (which? kb : qb) + (size_t)r*NPIX + ck*64 + c8*8;
            __half* dst = (which? ks : qs) + r*72 + c8*8;
            *(uint4*)dst = *(const uint4*)src;
        }
        __syncthreads();
        if (wid < 6){
            #pragma unroll
            for (int kst=0; kst<4; kst++){
                uint32_t Bf[2];
                ldm_x2(Bf, bAddr + kst*32);
                #pragma unroll
                for (int mi=0; mi<3; mi++){
                    uint32_t Af[4];
                    ldm_x4(Af, aAddr + mi*16*144 + kst*32);
                    mma16816f(acc[mi], Af[0],Af[1],Af[2],Af[3], Bf[0],Bf[1]);
                }
            }
        }
        __syncthreads();
    }
    if (wid < 6){
        int gi = lane>>2, li4 = lane&3;
        float* dst = g_spart + (size_t)(bh*ASEG+seg)*HD*HD;
        #pragma unroll
        for (int mi=0; mi<3; mi++){
            int r0 = mi*16 + gi;
            int cc = n0 + li4*2;
            dst[r0*HD+cc]     = acc[mi][0];
            dst[r0*HD+cc+1]   = acc[mi][1];
            dst[(r0+8)*HD+cc]   = acc[mi][2];
            dst[(r0+8)*HD+cc+1] = acc[mi][3];
        }
    }
}

// ---------------- combine partials, scale, softmax ----------------
__global__ void k_softmax(const float* __restrict__ temp){
    int row = blockIdx.x;
    int bh = row / HD;
    int i  = row - bh*HD;
    int b = bh >> 2, hh = bh & 3;
    int j = threadIdx.x;
    float v = -1e30f;
    if (j < HD){
        float s = 0.f;
        #pragma unroll
        for (int sg=0; sg<ASEG; sg++)
            s += g_spart[((size_t)(bh*ASEG+sg)*HD + i)*HD + j];
        v = s * __ldg(&temp[hh]) * g_inq[b*C + hh*HD + i] * g_ink[b*C + hh*HD + j];
    }
    __shared__ float sh[64];
    sh[j] = v; __syncthreads();
    for (int o=32;o>0;o>>=1){ if (j<o) sh[j]=fmaxf(sh[j],sh[j+o]); __syncthreads(); }
    float m = sh[0]; __syncthreads();
    float e = (j < HD) ? expf(v - m) : 0.f;
    sh[j] = e; __syncthreads();
    for (int o=32;o>0;o>>=1){ if (j<o) sh[j]+=sh[j+o]; __syncthreads(); }
    if (j < HD) g_attn[(size_t)bh*HD*HD + i*HD + j] = e / sh[0];
}

// ================= fused (attn@v)*sigmoid(gate) + proj GEMM =================
#define WS_V  0
#define WS_G  13056
#define WS_AT 26112
#define S_OF  51200
#define SMEMP 103424

__global__ __launch_bounds__(256)
void k_avproj(const __half* __restrict__ wp, float* __restrict__ outg){
    extern __shared__ __align__(16) char smem[];
    uint32_t sb = su32(smem);
    int b = blockIdx.y, pt = blockIdx.x;
    int p0 = pt*128;
    int tid = threadIdx.x, wid = tid>>5, lane = tid&31;
    int gi = lane>>2, li4 = lane&3;
    __half* of_s = (__half*)(smem + S_OF);
    __half* at_s = (__half*)(smem + WS_AT);

    // ---------- phase 1: of panel ----------
    for (int h=0; h<HEADS; h++){
        const __half* vb = g_dw + ((size_t)b*C4 + 3*C + h*HD)*NPIX + p0;
        const __half* gb = g_dw + ((size_t)b*C4 + C   + h*HD)*NPIX + p0;
        for (int e=tid; e<1536; e+=256){
            int which = e>=768;
            int idx = e - which*768;
            int r = idx>>4, ch = idx&15;
            const __half* src = (which? gb : vb) + (size_t)r*NPIX;
            CP16(sb + (which? WS_G : WS_V) + r*272 + ch*16, (const char*)src + ch*16);
        }
        asm volatile("cp.async.commit_group;" ::: "memory");
        const float* ap = g_attn + (size_t)(b*HEADS+h)*HD*HD;
        for (int e=tid; e<2304; e+=256){
            int i = e/48, j = e - (e/48)*48;
            at_s[i*56+j] = __float2half(ap[e]);
        }
        asm volatile("cp.async.wait_group 0;" ::: "memory");
        __syncthreads();

        int n0 = wid*16;
        float acc[3][2][4];
        #pragma unroll
        for (int mi=0;mi<3;mi++)
            #pragma unroll
            for (int ni=0;ni<2;ni++)
                #pragma unroll
                for (int r=0;r<4;r++) acc[mi][ni][r]=0.f;

        #pragma unroll
        for (int kst=0; kst<3; kst++){
            uint32_t Af[3][4], Bf[2][2];
            #pragma unroll
            for (int mi=0; mi<3; mi++)
                ldm_x4(Af[mi], sb + WS_AT + ((mi*16 + (lane&15))*56 + kst*16 + (lane>>4)*8)*2);
            #pragma unroll
            for (int ni=0; ni<2; ni++)
                ldm_x2t(Bf[ni], sb + WS_V + (kst*16 + (lane&15))*272 + (n0 + ni*8)*2);
            #pragma unroll
            for (int mi=0; mi<3; mi++)
                #pragma unroll
                for (int ni=0; ni<2; ni++)
                    mma16816f(acc[mi][ni], Af[mi][0],Af[mi][1],Af[mi][2],Af[mi][3],
                              Bf[ni][0],Bf[ni][1]);
        }

        const __half* gs = (const __half*)(smem + WS_G);
        #pragma unroll
        for (int mi=0; mi<3; mi++){
            #pragma unroll
            for (int ni=0; ni<2; ni++){
                int r0 = mi*16 + gi;
                int cc = n0 + ni*8 + li4*2;
                float2 g0 = __half22float2(*(const __half2*)&gs[r0*136 + cc]);
                *(__half2*)&of_s[(h*HD + r0)*136 + cc] =
                    __floats2half2_rn(acc[mi][ni][0]*sigmoidf_(g0.x),
                                      acc[mi][ni][1]*sigmoidf_(g0.y));
                float2 g1 = __half22float2(*(const __half2*)&gs[(r0+8)*136 + cc]);
                *(__half2*)&of_s[(h*HD + r0+8)*136 + cc] =
                    __floats2half2_rn(acc[mi][ni][2]*sigmoidf_(g1.x),
                                      acc[mi][ni][3]*sigmoidf_(g1.y));
            }
        }
        __syncthreads();
    }

    // ---------- phase 2: proj GEMM, B = of panel in smem ----------
    int wr = wid>>2, wc = wid&3;
    {
        for (int e=tid; e<1536; e+=256){
            int r = e/24, ch = e - (e/24)*24;
            CP16(sb + r*400 + ch*16, (const char*)(wp + (size_t)r*GK) + ch*16);
        }
        asm volatile("cp.async.commit_group;" ::: "memory");
    }
    uint32_t aBase = sb + ((wr*32 + (lane&15))*400) + (lane>>4)*16;
    uint32_t bA    = sb + S_OF + (lane&15)*272 + wc*64;

    for (int ot=0; ot<3; ot++){
        if (ot+1 < 3){
            int bm1 = (ot+1)*64;
            uint32_t dstb = sb + ((ot+1)&1)*A6SZ;
            for (int e=tid; e<1536; e+=256){
                int r = e/24, ch = e - (e/24)*24;
                CP16(dstb + r*400 + ch*16, (const char*)(wp + (size_t)(bm1+r)*GK) + ch*16);
            }
            asm volatile("cp.async.commit_group;" ::: "memory");
            asm volatile("cp.async.wait_group 1;" ::: "memory");
        } else {
            asm volatile("cp.async.wait_group 0;" ::: "memory");
        }
        __syncthreads();

        uint32_t aA = aBase + (ot&1)*A6SZ;
        float acc[2][4][4];
        #pragma unroll
        for (int i=0;i<2;i++)
            #pragma unroll
            for (int j=0;j<4;j++)
                #pragma unroll
                for (int r=0;r<4;r++) acc[i][j][r]=0.f;

        #pragma unroll
        for (int ks=0; ks<12; ks++){
            uint32_t Af[2][4], Bf[4][2];
            #pragma unroll
            for (int mi=0; mi<2; mi++) ldm_x4(Af[mi], aA + mi*6400 + ks*32);
            #pragma unroll
            for (int ni=0; ni<4; ni++) ldm_x2t(Bf[ni], bA + ks*4352 + ni*16);
            #pragma unroll
            for (int mi=0; mi<2; mi++)
                #pragma unroll
                for (int ni=0; ni<4; ni++)
                    mma16816f(acc[mi][ni], Af[mi][0],Af[mi][1],Af[mi][2],Af[mi][3],
                              Bf[ni][0],Bf[ni][1]);
        }

        int bm = ot*64;
        float* O = outg + (size_t)b*C*NPIX + p0;
        #pragma unroll
        for (int ni=0; ni<4; ni++){
            int n = wc*32 + ni*8 + li4*2;
            #pragma unroll
            for (int mi=0; mi<2; mi++){
                int m0 = bm + wr*32 + mi*16 + gi;
                *(float2*)(O + (size_t)m0*NPIX + n) =
                    make_float2(acc[mi][ni][0], acc[mi][ni][1]);
                *(float2*)(O + (size_t)(m0+8)*NPIX + n) =
                    make_float2(acc[mi][ni][2], acc[mi][ni][3]);
            }
        }
        __syncthreads();
    }
}

// ---------------- host ----------------
extern "C" void kernel_launch(void* const* d_in, const int* in_sizes, int n_in,
                              void* d_out, int out_size){
    const float* x      = (const float*)d_in[0];
    const float* w_fc1  = (const float*)d_in[1];
    const float* w_fc2  = (const float*)d_in[2];
    const float* w_sp   = (const float*)d_in[3];
    const float* w_qkv  = (const float*)d_in[4];
    const float* w_dw   = (const float*)d_in[5];
    const float* w_proj = (const float*)d_in[6];
    const float* temp   = (const float*)d_in[7];
    float* out = (float*)d_out;

    __half *wq, *wp, *qkv;
    float *sg;
    cudaGetSymbolAddress((void**)&wq,  g_wq);
    cudaGetSymbolAddress((void**)&wp,  g_wp);
    cudaGetSymbolAddress((void**)&qkv, g_qkv);
    cudaGetSymbolAddress((void**)&sg,  g_sg);

    cudaFuncSetAttribute(k_hmma6,  cudaFuncAttributeMaxDynamicSharedMemorySize, SMEM6);
    cudaFuncSetAttribute(k_avproj, cudaFuncAttributeMaxDynamicSharedMemorySize, SMEMP);

    // side stream + events, created once outside capture (first call is the
    // uncaptured correctness run); reused identically on every call.
    static cudaStream_t s2 = nullptr;
    static cudaEvent_t  eg = nullptr, ev = nullptr;
    if (!s2){
        cudaStreamCreateWithFlags(&s2, cudaStreamNonBlocking);
        cudaEventCreateWithFlags(&eg, cudaEventDisableTiming);
        cudaEventCreateWithFlags(&ev, cudaEventDisableTiming);
    }

    k_stats        <<<dim3(NTILE, NB), 256>>>(x);
    k_chan_gate    <<<NB, 192>>>(w_fc1, w_fc2);
    k_spatial_conv <<<NB*NPIX/256, 256>>>(w_sp);

    k_wcvt<<<(NB*C4*GK/4)/256, 256>>>(w_qkv, wq);
    k_pcvt<<<(C*GK/4 + 255)/256, 256>>>(w_proj, wp);

    // qkv = sg(p) * ((w_qkv*cg) @ x): fp32-B converted at staging, half out
    k_hmma6<<<NB*(NPIX/128), 256, SMEM6>>>(
        wq, (long)C4*GK, x, qkv, (long)C4*NPIX, sg, C4, 12);

    // fork: gate/v depthwise on side stream, concurrent with q/k + attention chain
    cudaEventRecord(eg, 0);
    cudaStreamWaitEvent(s2, eg, 0);
    k_dw2<<<NB*C2, 256, 0, s2>>>(w_dw, 1);      // gate, v
    cudaEventRecord(ev, s2);

    k_dw2<<<NB*C2, 256>>>(w_dw, 0);             // q, k + inverse norms
    k_attn_mma<<<dim3(NB*HEADS, ASEG), 256>>>();
    k_softmax  <<<NB*HEADS*HD, 64>>>(temp);

    // join, then fused (attn@v)*sigmoid(gate) + projection -> d_out
    cudaStreamWaitEvent(0, ev, 0);
    k_avproj<<<dim3(NPIX/128, NB), 256, SMEMP>>>(wp, out);
}

// round 16
// speedup vs baseline: 1.0813x; 1.0813x over previous
#include <cuda_runtime.h>
#include <cuda_fp16.h>
#include <math.h>
#include <stdint.h>

#define NB    8
#define C     192
#define C2    384
#define C4    768
#define HEADS 4
#define HD    48
#define HW    128
#define NPIX  16384
#define GK    192
#define ASEG  16
#define ASEGLEN (NPIX/ASEG)
#define NTILE 64

// ---------------- scratch (static device memory) ----------------
__device__ float g_cps[NB*NTILE*C];
__device__ float g_cpm[NB*NTILE*C];
__device__ float g_cg [NB*C];
__device__ float g_sp [NB*2*NPIX];
__device__ float g_sg [NB*NPIX];
__device__ __half g_wq [NB*C4*GK];
__device__ __half g_wp [C*GK];
__device__ __half g_qkv[(size_t)NB*C4*NPIX];
__device__ __half g_dw [(size_t)NB*C4*NPIX];
__device__ float g_inq [NB*C];
__device__ float g_ink [NB*C];
__device__ float g_spart[(size_t)NB*HEADS*ASEG*HD*HD];
__device__ float g_attn [(size_t)NB*HEADS*HD*HD];

__device__ __forceinline__ float sigmoidf_(float x){ return 1.f/(1.f+expf(-x)); }

__device__ __forceinline__ uint32_t su32(const void* p){
    uint32_t a;
    asm("{ .reg .u64 t; cvta.to.shared.u64 t, %1; cvt.u32.u64 %0, t; }" : "=r"(a) : "l"(p));
    return a;
}
#define CP16(dst, src) \
    asm volatile("cp.async.cg.shared.global [%0], [%1], 16;" :: "r"(dst), "l"(src))

__device__ __forceinline__ void ldm_x4(uint32_t* r, uint32_t addr){
    asm volatile("ldmatrix.sync.aligned.m8n8.x4.shared.b16 {%0,%1,%2,%3}, [%4];"
      : "=r"(r[0]),"=r"(r[1]),"=r"(r[2]),"=r"(r[3]) : "r"(addr));
}
__device__ __forceinline__ void ldm_x2(uint32_t* r, uint32_t addr){
    asm volatile("ldmatrix.sync.aligned.m8n8.x2.shared.b16 {%0,%1}, [%2];"
      : "=r"(r[0]),"=r"(r[1]) : "r"(addr));
}
__device__ __forceinline__ void ldm_x2t(uint32_t* r, uint32_t addr){
    asm volatile("ldmatrix.sync.aligned.m8n8.x2.trans.shared.b16 {%0,%1}, [%2];"
      : "=r"(r[0]),"=r"(r[1]) : "r"(addr));
}
__device__ __forceinline__ void mma16816f(float* c, uint32_t a0, uint32_t a1,
                                          uint32_t a2, uint32_t a3,
                                          uint32_t b0, uint32_t b1){
    asm volatile(
      "mma.sync.aligned.m16n8k16.row.col.f32.f16.f16.f32 "
      "{%0,%1,%2,%3},{%4,%5,%6,%7},{%8,%9},{%0,%1,%2,%3};"
      : "+f"(c[0]), "+f"(c[1]), "+f"(c[2]), "+f"(c[3])
      : "r"(a0), "r"(a1), "r"(a2), "r"(a3), "r"(b0), "r"(b1));
}

// ---------------- K1: one pass over x -> channel + pixel stats ----------------
__global__ __launch_bounds__(256)
void k_stats(const float* __restrict__ x){
    __shared__ float sps[8*256], spm[8*256];
    int tile = blockIdx.x, b = blockIdx.y;
    int tid = threadIdx.x, w = tid>>5, lane = tid&31;
    int p0 = tile*256;
    float ps[8], pm[8];
    #pragma unroll
    for (int i=0;i<8;i++){ ps[i]=0.f; pm[i]=-1e30f; }
    for (int ci=0; ci<24; ci++){
        int c = w*24 + ci;
        const float* row = x + ((size_t)b*C + c)*NPIX + p0;
        float cs = 0.f, cm = -1e30f;
        #pragma unroll
        for (int it=0; it<8; it++){
            float v = row[it*32 + lane];
            ps[it] += v; pm[it] = fmaxf(pm[it], v);
            cs += v;     cm = fmaxf(cm, v);
        }
        #pragma unroll
        for (int o=16;o;o>>=1){
            cs += __shfl_xor_sync(~0u, cs, o);
            cm = fmaxf(cm, __shfl_xor_sync(~0u, cm, o));
        }
        if (lane==0){
            g_cps[(b*NTILE + tile)*C + c] = cs;
            g_cpm[(b*NTILE + tile)*C + c] = cm;
        }
    }
    #pragma unroll
    for (int it=0; it<8; it++){
        sps[w*256 + it*32 + lane] = ps[it];
        spm[w*256 + it*32 + lane] = pm[it];
    }
    __syncthreads();
    if (tid < 256){
        int p = tid;
        float s = 0.f, m = -1e30f;
        #pragma unroll
        for (int ww=0; ww<8; ww++){
            s += sps[ww*256+p];
            m = fmaxf(m, spm[ww*256+p]);
        }
        g_sp[(size_t)b*2*NPIX + p0 + p]        = s*(1.f/C);
        g_sp[(size_t)b*2*NPIX + NPIX + p0 + p] = m;
    }
}

// ---------------- K2: SE channel gate MLP ----------------
__global__ void k_chan_gate(const float* __restrict__ w1, const float* __restrict__ w2){
    int b = blockIdx.x, t = threadIdx.x;
    __shared__ float pool[C2], sq[48];
    {
        float s = 0.f, m = -1e30f;
        for (int tile=0; tile<NTILE; tile++){
            s += g_cps[(b*NTILE + tile)*C + t];
            m = fmaxf(m, g_cpm[(b*NTILE + tile)*C + t]);
        }
        pool[t]   = s*(1.f/NPIX);
        pool[C+t] = m;
    }
    __syncthreads();
    if (t < 48){
        float a = 0.f;
        #pragma unroll 8
        for (int c=0;c<C2;c++) a += w1[t*C2+c]*pool[c];
        sq[t] = fmaxf(a, 0.f);
    }
    __syncthreads();
    float a = 0.f;
    #pragma unroll
    for (int s=0;s<48;s++) a += w2[t*48+s]*sq[s];
    g_cg[b*C+t] = sigmoidf_(a);
}

// ---------------- K3: 7x7 spatial conv + sigmoid ----------------
__global__ void k_spatial_conv(const float* __restrict__ ws){
    int idx = blockIdx.x*256 + threadIdx.x;
    int b = idx >> 14, p = idx & (NPIX-1);
    int y = p >> 7, xx = p & 127;
    float acc = 0.f;
    #pragma unroll
    for (int ch=0; ch<2; ch++){
        const float* base = g_sp + (size_t)b*2*NPIX + (size_t)ch*NPIX;
        #pragma unroll
        for (int dy=-3; dy<=3; dy++){
            int yy = y+dy;
            if ((unsigned)yy < 128u){
                const float* row = base + yy*HW;
                #pragma unroll
                for (int dx=-3; dx<=3; dx++){
                    int xc = xx+dx;
                    if ((unsigned)xc < 128u)
                        acc += row[xc]*__ldg(&ws[ch*49 + (dy+3)*7 + (dx+3)]);
                }
            }
        }
    }
    g_sg[(size_t)b*NPIX + p] = sigmoidf_(acc);
}

// ---------------- merged weight conversion (qkv gate-folded + proj) ----------------
#define WQ_ELEMS (NB*C4*GK)
#define WP_ELEMS (C*GK)
__global__ void k_wcvt2(const float* __restrict__ wq_f, const float* __restrict__ wp_f,
                        __half* __restrict__ oq, __half* __restrict__ op){
    size_t i = ((size_t)blockIdx.x*256 + threadIdx.x)*4;
    if (i < WQ_ELEMS){
        int b  = (int)(i/(C4*GK));
        int rc = (int)(i - (size_t)b*C4*GK);
        int col = rc % GK;
        float4 v = *(const float4*)(wq_f+rc);
        const float* g = g_cg + b*C;
        v.x *= g[col]; v.y *= g[col+1]; v.z *= g[col+2]; v.w *= g[col+3];
        __half2 a = __floats2half2_rn(v.x, v.y);
        __half2 bb = __floats2half2_rn(v.z, v.w);
        *(uint2*)(oq+i) = make_uint2(*(uint32_t*)&a, *(uint32_t*)&bb);
    } else {
        size_t j = i - WQ_ELEMS;
        if (j < WP_ELEMS){
            float4 v = *(const float4*)(wp_f+j);
            __half2 a = __floats2half2_rn(v.x, v.y);
            __half2 bb = __floats2half2_rn(v.z, v.w);
            *(uint2*)(op+j) = make_uint2(*(uint32_t*)&a, *(uint32_t*)&bb);
        }
    }
}

// ================= qkv GEMM: fp32-B staged+converted, A ping-pong cp.async =================
#define S_A6 0
#define A6SZ 25600
#define S_B6 51200
#define SMEM6 103424

__global__ __launch_bounds__(256)
void k_hmma6(const __half* __restrict__ Ag, long sA,
             const float* __restrict__ Bg,
             __half* __restrict__ outp, long sC,
             const float* __restrict__ S, int M, int Mtiles){
    extern __shared__ __align__(16) char smem[];
    uint32_t sb = su32(smem);
    int b = blockIdx.x & 7, bn = (blockIdx.x >> 3)*128;
    const __half* A = Ag + (size_t)b*sA;
    const float* B = Bg + (size_t)b*C*NPIX;
    const float* Sp = S + (size_t)b*NPIX;

    int tid = threadIdx.x, wid = tid>>5, lane = tid&31;
    int wr = wid>>2, wc = wid&3;
    int gi = lane>>2, li4 = lane&3;

    for (int e=tid; e<1536; e+=256){
        int r = e/24, ch = e - (e/24)*24;
        CP16(sb + S_A6 + r*400 + ch*16, (const char*)(A + (size_t)r*GK) + ch*16);
    }
    asm volatile("cp.async.commit_group;" ::: "memory");

    for (int e=tid; e<6144; e+=256){
        int k = e>>5, c4 = e&31;
        float4 v = *(const float4*)(B + (size_t)k*NPIX + bn + c4*4);
        __half2 h0 = __floats2half2_rn(v.x, v.y);
        __half2 h1 = __floats2half2_rn(v.z, v.w);
        *(uint2*)(smem + S_B6 + k*272 + c4*8) = make_uint2(*(uint32_t*)&h0, *(uint32_t*)&h1);
    }

    uint32_t aBase = sb + S_A6 + ((wr*32 + (lane&15))*400) + (lane>>4)*16;
    uint32_t bA    = sb + S_B6 + (lane&15)*272 + wc*64;

    for (int ot=0; ot<Mtiles; ot++){
        if (ot+1 < Mtiles){
            int bm1 = (ot+1)*64;
            uint32_t dstb = sb + S_A6 + ((ot+1)&1)*A6SZ;
            for (int e=tid; e<1536; e+=256){
                int r = e/24, ch = e - (e/24)*24;
                CP16(dstb + r*400 + ch*16, (const char*)(A + (size_t)(bm1+r)*GK) + ch*16);
            }
            asm volatile("cp.async.commit_group;" ::: "memory");
            asm volatile("cp.async.wait_group 1;" ::: "memory");
        } else {
            asm volatile("cp.async.wait_group 0;" ::: "memory");
        }
        __syncthreads();

        uint32_t aA = aBase + (ot&1)*A6SZ;
        float acc[2][4][4];
        #pragma unroll
        for (int i=0;i<2;i++)
            #pragma unroll
            for (int j=0;j<4;j++)
                #pragma unroll
                for (int r=0;r<4;r++) acc[i][j][r]=0.f;

        #pragma unroll
        for (int ks=0; ks<12; ks++){
            uint32_t Af[2][4], Bf[4][2];
            #pragma unroll
            for (int mi=0; mi<2; mi++) ldm_x4(Af[mi], aA + mi*6400 + ks*32);
            #pragma unroll
            for (int ni=0; ni<4; ni++) ldm_x2t(Bf[ni], bA + ks*4352 + ni*16);
            #pragma unroll
            for (int mi=0; mi<2; mi++)
                #pragma unroll
                for (int ni=0; ni<4; ni++)
                    mma16816f(acc[mi][ni], Af[mi][0],Af[mi][1],Af[mi][2],Af[mi][3],
                              Bf[ni][0],Bf[ni][1]);
        }

        int bm = ot*64;
        __half* O = outp + (size_t)b*sC;
        #pragma unroll
        for (int ni=0; ni<4; ni++){
            int n = bn + wc*32 + ni*8 + li4*2;
            float2 sv = *(const float2*)&Sp[n];
            #pragma unroll
            for (int mi=0; mi<2; mi++){
                int m0 = bm + wr*32 + mi*16 + gi;
                *(__half2*)(O + (size_t)m0*NPIX + n) =
                    __floats2half2_rn(acc[mi][ni][0]*sv.x, acc[mi][ni][1]*sv.y);
                *(__half2*)(O + (size_t)(m0+8)*NPIX + n) =
                    __floats2half2_rn(acc[mi][ni][2]*sv.x, acc[mi][ni][3]*sv.y);
            }
        }
        __syncthreads();
    }
}

// ---------------- depthwise 3x3, full channel image per block + inv-norm ----------------
#define DWP 144
__global__ __launch_bounds__(256)
void k_dw2(const float* __restrict__ wd){
    __shared__ __half img[128*DWP];
    __shared__ float wsum[8];
    int bc = blockIdx.x;
    int ch = bc % C4;
    int b  = bc / C4;
    int tid = threadIdx.x;
    const __half* in = g_qkv + (size_t)bc*NPIX;

    float w[9];
    #pragma unroll
    for (int k=0;k<9;k++) w[k] = __ldg(&wd[ch*9+k]);

    for (int r=tid; r<128; r+=256){
        *(uint4*)&img[r*DWP]       = make_uint4(0,0,0,0);
        *(uint4*)&img[r*DWP + 136] = make_uint4(0,0,0,0);
    }
    for (int i=tid; i<2048; i+=256){
        int r = i>>4, c = i&15;
        *(uint4*)&img[r*DWP + 8 + c*8] = ((const uint4*)in)[i];
    }
    __syncthreads();

    __half* op = g_dw + (size_t)bc*NPIX;
    float ssq = 0.f;
    #pragma unroll
    for (int it=0; it<8; it++){
        int idx = it*256 + tid;
        int r  = idx>>4;
        int x0 = (idx&15)*8;
        float acc[8] = {0.f,0.f,0.f,0.f,0.f,0.f,0.f,0.f};
        #pragma unroll
        for (int dr=-1; dr<=1; dr++){
            int rr = r + dr;
            if ((unsigned)rr < 128u){
                const __half* rp = &img[rr*DWP + x0 + 6];
                float f[12];
                #pragma unroll
                for (int j=0;j<6;j++){
                    float2 p = __half22float2(*(const __half2*)(rp + 2*j));
                    f[2*j] = p.x; f[2*j+1] = p.y;
                }
                float w0 = w[(dr+1)*3], w1 = w[(dr+1)*3+1], w2 = w[(dr+1)*3+2];
                #pragma unroll
                for (int u=0;u<8;u++)
                    acc[u] += w0*f[u+1] + w1*f[u+2] + w2*f[u+3];
            }
        }
        __align__(16) __half hv[8];
        #pragma unroll
        for (int u=0;u<8;u++){ hv[u] = __float2half(acc[u]); ssq += acc[u]*acc[u]; }
        ((uint4*)op)[idx] = *(uint4*)hv;
    }

    int slot = (ch < C) ? 0 : ((ch >= 2*C && ch < 3*C) ? 1 : -1);
    if (slot >= 0){
        #pragma unroll
        for (int o=16;o;o>>=1) ssq += __shfl_xor_sync(~0u, ssq, o);
        if ((tid&31)==0) wsum[tid>>5] = ssq;
        __syncthreads();
        if (tid==0){
            float s = 0.f;
            #pragma unroll
            for (int i=0;i<8;i++) s += wsum[i];
            float inv = 1.f/fmaxf(sqrtf(s), 1e-12f);
            if (slot==0) g_inq[b*C + ch]       = inv;
            else         g_ink[b*C + ch - 2*C] = inv;
        }
    }
}

// ---------------- q.k^T partials on tensor cores (ASEG=16 for load balance) ----------------
__global__ __launch_bounds__(256)
void k_attn_mma(){
    __shared__ __half qs[48*72];
    __shared__ __half ks[48*72];
    int bh = blockIdx.x, seg = blockIdx.y;
    int b = bh>>2, hh = bh&3;
    const __half* qb = g_dw + ((size_t)b*C4 + hh*HD)*NPIX + seg*ASEGLEN;
    const __half* kb = g_dw + ((size_t)b*C4 + 2*C + hh*HD)*NPIX + seg*ASEGLEN;
    int tid = threadIdx.x, wid = tid>>5, lane = tid&31;
    uint32_t qsb = su32(qs), ksb = su32(ks);
    int n0 = wid*8;

    float acc[3][4];
    #pragma unroll
    for (int mi=0;mi<3;mi++)
        #pragma unroll
        for (int r=0;r<4;r++) acc[mi][r]=0.f;

    uint32_t aAddr = qsb + ((lane&15)*72 + (lane>>4)*8)*2;
    uint32_t bAddr = ksb + (((n0 + (lane&7))*72) + (((lane>>3)&1)*8))*2;

    for (int ck=0; ck<ASEGLEN/64; ck++){
        for (int e=tid; e<768; e+=256){
            int which = e>=384;
            int idx = e - which*384;
            int r = idx>>3, c8 = idx&7;
            const __half* src = (which? kb : qb) + (size_t)r*NPIX + ck*64 + c8*8;
            __half* dst = (which? ks : qs) + r*72 + c8*8;
            *(uint4*)dst = *(const uint4*)src;
        }
        __syncthreads();
        if (wid < 6){
            #pragma unroll
            for (int kst=0; kst<4; kst++){
                uint32_t Bf[2];
                ldm_x2(Bf, bAddr + kst*32);
                #pragma unroll
                for (int mi=0; mi<3; mi++){
                    uint32_t Af[4];
                    ldm_x4(Af, aAddr + mi*16*144 + kst*32);
                    mma16816f(acc[mi], Af[0],Af[1],Af[2],Af[3], Bf[0],Bf[1]);
                }
            }
        }
        __syncthreads();
    }
    if (wid < 6){
        int gi = lane>>2, li4 = lane&3;
        float* dst = g_spart + (size_t)(bh*ASEG+seg)*HD*HD;
        #pragma unroll
        for (int mi=0; mi<3; mi++){
            int r0 = mi*16 + gi;
            int cc = n0 + li4*2;
            dst[r0*HD+cc]     = acc[mi][0];
            dst[r0*HD+cc+1]   = acc[mi][1];
            dst[(r0+8)*HD+cc]   = acc[mi][2];
            dst[(r0+8)*HD+cc+1] = acc[mi][3];
        }
    }
}

// ---------------- combine partials, scale, softmax ----------------
__global__ void k_softmax(const float* __restrict__ temp){
    int row = blockIdx.x;
    int bh = row / HD;
    int i  = row - bh*HD;
    int b = bh >> 2, hh = bh & 3;
    int j = threadIdx.x;
    float v = -1e30f;
    if (j < HD){
        float s = 0.f;
        #pragma unroll
        for (int sg=0; sg<ASEG; sg++)
            s += g_spart[((size_t)(bh*ASEG+sg)*HD + i)*HD + j];
        v = s * __ldg(&temp[hh]) * g_inq[b*C + hh*HD + i] * g_ink[b*C + hh*HD + j];
    }
    __shared__ float sh[64];
    sh[j] = v; __syncthreads();
    for (int o=32;o>0;o>>=1){ if (j<o) sh[j]=fmaxf(sh[j],sh[j+o]); __syncthreads(); }
    float m = sh[0]; __syncthreads();
    float e = (j < HD) ? expf(v - m) : 0.f;
    sh[j] = e; __syncthreads();
    for (int o=32;o>0;o>>=1){ if (j<o) sh[j]+=sh[j+o]; __syncthreads(); }
    if (j < HD) g_attn[(size_t)bh*HD*HD + i*HD + j] = e / sh[0];
}

// ================= fused (attn@v)*sigmoid(gate) + proj GEMM =================
#define WS_V  0
#define WS_G  13056
#define WS_AT 26112
#define S_OF  51200
#define SMEMP 103424

__global__ __launch_bounds__(256)
void k_avproj(const __half* __restrict__ wp, float* __restrict__ outg){
    extern __shared__ __align__(16) char smem[];
    uint32_t sb = su32(smem);
    int b = blockIdx.y, pt = blockIdx.x;
    int p0 = pt*128;
    int tid = threadIdx.x, wid = tid>>5, lane = tid&31;
    int gi = lane>>2, li4 = lane&3;
    __half* of_s = (__half*)(smem + S_OF);
    __half* at_s = (__half*)(smem + WS_AT);

    // ---------- phase 1: of panel ----------
    for (int h=0; h<HEADS; h++){
        const __half* vb = g_dw + ((size_t)b*C4 + 3*C + h*HD)*NPIX + p0;
        const __half* gb = g_dw + ((size_t)b*C4 + C   + h*HD)*NPIX + p0;
        for (int e=tid; e<1536; e+=256){
            int which = e>=768;
            int idx = e - which*768;
            int r = idx>>4, ch = idx&15;
            const __half* src = (which? gb : vb) + (size_t)r*NPIX;
            CP16(sb + (which? WS_G : WS_V) + r*272 + ch*16, (const char*)src + ch*16);
        }
        asm volatile("cp.async.commit_group;" ::: "memory");
        const float* ap = g_attn + (size_t)(b*HEADS+h)*HD*HD;
        for (int e=tid; e<2304; e+=256){
            int i = e/48, j = e - (e/48)*48;
            at_s[i*56+j] = __float2half(ap[e]);
        }
        asm volatile("cp.async.wait_group 0;" ::: "memory");
        __syncthreads();

        int n0 = wid*16;
        float acc[3][2][4];
        #pragma unroll
        for (int mi=0;mi<3;mi++)
            #pragma unroll
            for (int ni=0;ni<2;ni++)
                #pragma unroll
                for (int r=0;r<4;r++) acc[mi][ni][r]=0.f;

        #pragma unroll
        for (int kst=0; kst<3; kst++){
            uint32_t Af[3][4], Bf[2][2];
            #pragma unroll
            for (int mi=0; mi<3; mi++)
                ldm_x4(Af[mi], sb + WS_AT + ((mi*16 + (lane&15))*56 + kst*16 + (lane>>4)*8)*2);
            #pragma unroll
            for (int ni=0; ni<2; ni++)
                ldm_x2t(Bf[ni], sb + WS_V + (kst*16 + (lane&15))*272 + (n0 + ni*8)*2);
            #pragma unroll
            for (int mi=0; mi<3; mi++)
                #pragma unroll
                for (int ni=0; ni<2; ni++)
                    mma16816f(acc[mi][ni], Af[mi][0],Af[mi][1],Af[mi][2],Af[mi][3],
                              Bf[ni][0],Bf[ni][1]);
        }

        const __half* gs = (const __half*)(smem + WS_G);
        #pragma unroll
        for (int mi=0; mi<3; mi++){
            #pragma unroll
            for (int ni=0; ni<2; ni++){
                int r0 = mi*16 + gi;
                int cc = n0 + ni*8 + li4*2;
                float2 g0 = __half22float2(*(const __half2*)&gs[r0*136 + cc]);
                *(__half2*)&of_s[(h*HD + r0)*136 + cc] =
                    __floats2half2_rn(acc[mi][ni][0]*sigmoidf_(g0.x),
                                      acc[mi][ni][1]*sigmoidf_(g0.y));
                float2 g1 = __half22float2(*(const __half2*)&gs[(r0+8)*136 + cc]);
                *(__half2*)&of_s[(h*HD + r0+8)*136 + cc] =
                    __floats2half2_rn(acc[mi][ni][2]*sigmoidf_(g1.x),
                                      acc[mi][ni][3]*sigmoidf_(g1.y));
            }
        }
        __syncthreads();
    }

    // ---------- phase 2: proj GEMM, B = of panel in smem ----------
    int wr = wid>>2, wc = wid&3;
    {
        for (int e=tid; e<1536; e+=256){
            int r = e/24, ch = e - (e/24)*24;
            CP16(sb + r*400 + ch*16, (const char*)(wp + (size_t)r*GK) + ch*16);
        }
        asm volatile("cp.async.commit_group;" ::: "memory");
    }
    uint32_t aBase = sb + ((wr*32 + (lane&15))*400) + (lane>>4)*16;
    uint32_t bA    = sb + S_OF + (lane&15)*272 + wc*64;

    for (int ot=0; ot<3; ot++){
        if (ot+1 < 3){
            int bm1 = (ot+1)*64;
            uint32_t dstb = sb + ((ot+1)&1)*A6SZ;
            for (int e=tid; e<1536; e+=256){
                int r = e/24, ch = e - (e/24)*24;
                CP16(dstb + r*400 + ch*16, (const char*)(wp + (size_t)(bm1+r)*GK) + ch*16);
            }
            asm volatile("cp.async.commit_group;" ::: "memory");
            asm volatile("cp.async.wait_group 1;" ::: "memory");
        } else {
            asm volatile("cp.async.wait_group 0;" ::: "memory");
        }
        __syncthreads();

        uint32_t aA = aBase + (ot&1)*A6SZ;
        float acc[2][4][4];
        #pragma unroll
        for (int i=0;i<2;i++)
            #pragma unroll
            for (int j=0;j<4;j++)
                #pragma unroll
                for (int r=0;r<4;r++) acc[i][j][r]=0.f;

        #pragma unroll
        for (int ks=0; ks<12; ks++){
            uint32_t Af[2][4], Bf[4][2];
            #pragma unroll
            for (int mi=0; mi<2; mi++) ldm_x4(Af[mi], aA + mi*6400 + ks*32);
            #pragma unroll
            for (int ni=0; ni<4; ni++) ldm_x2t(Bf[ni], bA + ks*4352 + ni*16);
            #pragma unroll
            for (int mi=0; mi<2; mi++)
                #pragma unroll
                for (int ni=0; ni<4; ni++)
                    mma16816f(acc[mi][ni], Af[mi][0],Af[mi][1],Af[mi][2],Af[mi][3],
                              Bf[ni][0],Bf[ni][1]);
        }

        int bm = ot*64;
        float* O = outg + (size_t)b*C*NPIX + p0;
        #pragma unroll
        for (int ni=0; ni<4; ni++){
            int n = wc*32 + ni*8 + li4*2;
            #pragma unroll
            for (int mi=0; mi<2; mi++){
                int m0 = bm + wr*32 + mi*16 + gi;
                *(float2*)(O + (size_t)m0*NPIX + n) =
                    make_float2(acc[mi][ni][0], acc[mi][ni][1]);
                *(float2*)(O + (size_t)(m0+8)*NPIX + n) =
                    make_float2(acc[mi][ni][2], acc[mi][ni][3]);
            }
        }
        __syncthreads();
    }
}

// ---------------- host ----------------
extern "C" void kernel_launch(void* const* d_in, const int* in_sizes, int n_in,
                              void* d_out, int out_size){
    const float* x      = (const float*)d_in[0];
    const float* w_fc1  = (const float*)d_in[1];
    const float* w_fc2  = (const float*)d_in[2];
    const float* w_sp   = (const float*)d_in[3];
    const float* w_qkv  = (const float*)d_in[4];
    const float* w_dw   = (const float*)d_in[5];
    const float* w_proj = (const float*)d_in[6];
    const float* temp   = (const float*)d_in[7];
    float* out = (float*)d_out;

    __half *wq, *wp, *qkv;
    float *sg;
    cudaGetSymbolAddress((void**)&wq,  g_wq);
    cudaGetSymbolAddress((void**)&wp,  g_wp);
    cudaGetSymbolAddress((void**)&qkv, g_qkv);
    cudaGetSymbolAddress((void**)&sg,  g_sg);

    cudaFuncSetAttribute(k_hmma6,  cudaFuncAttributeMaxDynamicSharedMemorySize, SMEM6);
    cudaFuncSetAttribute(k_avproj, cudaFuncAttributeMaxDynamicSharedMemorySize, SMEMP);

    k_stats        <<<dim3(NTILE, NB), 256>>>(x);
    k_chan_gate    <<<NB, 192>>>(w_fc1, w_fc2);
    k_spatial_conv <<<NB*NPIX/256, 256>>>(w_sp);

    k_wcvt2<<<((WQ_ELEMS + WP_ELEMS)/4 + 255)/256, 256>>>(w_qkv, w_proj, wq, wp);

    // qkv = sg(p) * ((w_qkv*cg) @ x): fp32-B converted at staging, half out
    k_hmma6<<<NB*(NPIX/128), 256, SMEM6>>>(
        wq, (long)C4*GK, x, qkv, (long)C4*NPIX, sg, C4, 12);

    k_dw2<<<NB*C4, 256>>>(w_dw);     // dw + inverse norms

    k_attn_mma<<<dim3(NB*HEADS, ASEG), 256>>>();
    k_softmax  <<<NB*HEADS*HD, 64>>>(temp);

    // fused (attn@v)*sigmoid(gate) + projection -> d_out
    k_avproj<<<dim3(NPIX/128, NB), 256, SMEMP>>>(wp, out);
}

// round 17
// speedup vs baseline: 1.1638x; 1.0763x over previous
#include <cuda_runtime.h>
#include <cuda_fp16.h>
#include <math.h>
#include <stdint.h>

#define NB    8
#define C     192
#define C2    384
#define C4    768
#define HEADS 4
#define HD    48
#define HW    128
#define NPIX  16384
#define GK    192
#define ASEG  16
#define ASEGLEN (NPIX/ASEG)
#define NTILE 64

// ---------------- scratch (static device memory) ----------------
__device__ float g_cps[NB*NTILE*C];
__device__ float g_cpm[NB*NTILE*C];
__device__ float g_cg [NB*C];
__device__ float g_sp [NB*2*NPIX];
__device__ float g_sg [NB*NPIX];
__device__ __half g_wq [NB*C4*GK];
__device__ __half g_wp [C*GK];
__device__ __half g_qkv[(size_t)NB*C4*NPIX];
__device__ __half g_dw [(size_t)NB*C4*NPIX];
__device__ float g_inq [NB*C];
__device__ float g_ink [NB*C];
__device__ float g_spart[(size_t)NB*HEADS*ASEG*HD*HD];
__device__ float g_attn [(size_t)NB*HEADS*HD*HD];

__device__ __forceinline__ float sigmoidf_(float x){ return 1.f/(1.f+expf(-x)); }

__device__ __forceinline__ uint32_t su32(const void* p){
    uint32_t a;
    asm("{ .reg .u64 t; cvta.to.shared.u64 t, %1; cvt.u32.u64 %0, t; }" : "=r"(a) : "l"(p));
    return a;
}
#define CP16(dst, src) \
    asm volatile("cp.async.cg.shared.global [%0], [%1], 16;" :: "r"(dst), "l"(src))

__device__ __forceinline__ void ldm_x4(uint32_t* r, uint32_t addr){
    asm volatile("ldmatrix.sync.aligned.m8n8.x4.shared.b16 {%0,%1,%2,%3}, [%4];"
      : "=r"(r[0]),"=r"(r[1]),"=r"(r[2]),"=r"(r[3]) : "r"(addr));
}
__device__ __forceinline__ void ldm_x2(uint32_t* r, uint32_t addr){
    asm volatile("ldmatrix.sync.aligned.m8n8.x2.shared.b16 {%0,%1}, [%2];"
      : "=r"(r[0]),"=r"(r[1]) : "r"(addr));
}
__device__ __forceinline__ void ldm_x2t(uint32_t* r, uint32_t addr){
    asm volatile("ldmatrix.sync.aligned.m8n8.x2.trans.shared.b16 {%0,%1}, [%2];"
      : "=r"(r[0]),"=r"(r[1]) : "r"(addr));
}
__device__ __forceinline__ void mma16816f(float* c, uint32_t a0, uint32_t a1,
                                          uint32_t a2, uint32_t a3,
                                          uint32_t b0, uint32_t b1){
    asm volatile(
      "mma.sync.aligned.m16n8k16.row.col.f32.f16.f16.f32 "
      "{%0,%1,%2,%3},{%4,%5,%6,%7},{%8,%9},{%0,%1,%2,%3};"
      : "+f"(c[0]), "+f"(c[1]), "+f"(c[2]), "+f"(c[3])
      : "r"(a0), "r"(a1), "r"(a2), "r"(a3), "r"(b0), "r"(b1));
}

// ---------------- K1: one pass over x -> channel + pixel stats ----------------
__global__ __launch_bounds__(256)
void k_stats(const float* __restrict__ x){
    __shared__ float sps[8*256], spm[8*256];
    int tile = blockIdx.x, b = blockIdx.y;
    int tid = threadIdx.x, w = tid>>5, lane = tid&31;
    int p0 = tile*256;
    float ps[8], pm[8];
    #pragma unroll
    for (int i=0;i<8;i++){ ps[i]=0.f; pm[i]=-1e30f; }
    for (int ci=0; ci<24; ci++){
        int c = w*24 + ci;
        const float* row = x + ((size_t)b*C + c)*NPIX + p0;
        float cs = 0.f, cm = -1e30f;
        #pragma unroll
        for (int it=0; it<8; it++){
            float v = row[it*32 + lane];
            ps[it] += v; pm[it] = fmaxf(pm[it], v);
            cs += v;     cm = fmaxf(cm, v);
        }
        #pragma unroll
        for (int o=16;o;o>>=1){
            cs += __shfl_xor_sync(~0u, cs, o);
            cm = fmaxf(cm, __shfl_xor_sync(~0u, cm, o));
        }
        if (lane==0){
            g_cps[(b*NTILE + tile)*C + c] = cs;
            g_cpm[(b*NTILE + tile)*C + c] = cm;
        }
    }
    #pragma unroll
    for (int it=0; it<8; it++){
        sps[w*256 + it*32 + lane] = ps[it];
        spm[w*256 + it*32 + lane] = pm[it];
    }
    __syncthreads();
    if (tid < 256){
        int p = tid;
        float s = 0.f, m = -1e30f;
        #pragma unroll
        for (int ww=0; ww<8; ww++){
            s += sps[ww*256+p];
            m = fmaxf(m, spm[ww*256+p]);
        }
        g_sp[(size_t)b*2*NPIX + p0 + p]        = s*(1.f/C);
        g_sp[(size_t)b*2*NPIX + NPIX + p0 + p] = m;
    }
}

// ---------------- K2: SE channel gate MLP ----------------
__global__ void k_chan_gate(const float* __restrict__ w1, const float* __restrict__ w2){
    int b = blockIdx.x, t = threadIdx.x;
    __shared__ float pool[C2], sq[48];
    {
        float s = 0.f, m = -1e30f;
        for (int tile=0; tile<NTILE; tile++){
            s += g_cps[(b*NTILE + tile)*C + t];
            m = fmaxf(m, g_cpm[(b*NTILE + tile)*C + t]);
        }
        pool[t]   = s*(1.f/NPIX);
        pool[C+t] = m;
    }
    __syncthreads();
    if (t < 48){
        float a = 0.f;
        #pragma unroll 8
        for (int c=0;c<C2;c++) a += w1[t*C2+c]*pool[c];
        sq[t] = fmaxf(a, 0.f);
    }
    __syncthreads();
    float a = 0.f;
    #pragma unroll
    for (int s=0;s<48;s++) a += w2[t*48+s]*sq[s];
    g_cg[b*C+t] = sigmoidf_(a);
}

// ---------------- K3: 7x7 spatial conv + sigmoid ----------------
__global__ void k_spatial_conv(const float* __restrict__ ws){
    int idx = blockIdx.x*256 + threadIdx.x;
    int b = idx >> 14, p = idx & (NPIX-1);
    int y = p >> 7, xx = p & 127;
    float acc = 0.f;
    #pragma unroll
    for (int ch=0; ch<2; ch++){
        const float* base = g_sp + (size_t)b*2*NPIX + (size_t)ch*NPIX;
        #pragma unroll
        for (int dy=-3; dy<=3; dy++){
            int yy = y+dy;
            if ((unsigned)yy < 128u){
                const float* row = base + yy*HW;
                #pragma unroll
                for (int dx=-3; dx<=3; dx++){
                    int xc = xx+dx;
                    if ((unsigned)xc < 128u)
                        acc += row[xc]*__ldg(&ws[ch*49 + (dy+3)*7 + (dx+3)]);
                }
            }
        }
    }
    g_sg[(size_t)b*NPIX + p] = sigmoidf_(acc);
}

// ---------------- merged weight conversion (qkv gate-folded + proj) ----------------
#define WQ_ELEMS (NB*C4*GK)
#define WP_ELEMS (C*GK)
__global__ void k_wcvt2(const float* __restrict__ wq_f, const float* __restrict__ wp_f,
                        __half* __restrict__ oq, __half* __restrict__ op){
    size_t i = ((size_t)blockIdx.x*256 + threadIdx.x)*4;
    if (i < WQ_ELEMS){
        int b  = (int)(i/(C4*GK));
        int rc = (int)(i - (size_t)b*C4*GK);
        int col = rc % GK;
        float4 v = *(const float4*)(wq_f+rc);
        const float* g = g_cg + b*C;
        v.x *= g[col]; v.y *= g[col+1]; v.z *= g[col+2]; v.w *= g[col+3];
        __half2 a = __floats2half2_rn(v.x, v.y);
        __half2 bb = __floats2half2_rn(v.z, v.w);
        *(uint2*)(oq+i) = make_uint2(*(uint32_t*)&a, *(uint32_t*)&bb);
    } else {
        size_t j = i - WQ_ELEMS;
        if (j < WP_ELEMS){
            float4 v = *(const float4*)(wp_f+j);
            __half2 a = __floats2half2_rn(v.x, v.y);
            __half2 bb = __floats2half2_rn(v.z, v.w);
            *(uint2*)(op+j) = make_uint2(*(uint32_t*)&a, *(uint32_t*)&bb);
        }
    }
}

// ================= qkv GEMM: fp32-B staged+converted, A ping-pong cp.async =================
#define S_A6 0
#define A6SZ 25600
#define S_B6 51200
#define SMEM6 103424

__global__ __launch_bounds__(256)
void k_hmma6(const __half* __restrict__ Ag, long sA,
             const float* __restrict__ Bg,
             __half* __restrict__ outp, long sC,
             const float* __restrict__ S, int M, int Mtiles){
    extern __shared__ __align__(16) char smem[];
    uint32_t sb = su32(smem);
    int b = blockIdx.x & 7, bn = (blockIdx.x >> 3)*128;
    const __half* A = Ag + (size_t)b*sA;
    const float* B = Bg + (size_t)b*C*NPIX;
    const float* Sp = S + (size_t)b*NPIX;

    int tid = threadIdx.x, wid = tid>>5, lane = tid&31;
    int wr = wid>>2, wc = wid&3;
    int gi = lane>>2, li4 = lane&3;

    for (int e=tid; e<1536; e+=256){
        int r = e/24, ch = e - (e/24)*24;
        CP16(sb + S_A6 + r*400 + ch*16, (const char*)(A + (size_t)r*GK) + ch*16);
    }
    asm volatile("cp.async.commit_group;" ::: "memory");

    for (int e=tid; e<6144; e+=256){
        int k = e>>5, c4 = e&31;
        float4 v = *(const float4*)(B + (size_t)k*NPIX + bn + c4*4);
        __half2 h0 = __floats2half2_rn(v.x, v.y);
        __half2 h1 = __floats2half2_rn(v.z, v.w);
        *(uint2*)(smem + S_B6 + k*272 + c4*8) = make_uint2(*(uint32_t*)&h0, *(uint32_t*)&h1);
    }

    uint32_t aBase = sb + S_A6 + ((wr*32 + (lane&15))*400) + (lane>>4)*16;
    uint32_t bA    = sb + S_B6 + (lane&15)*272 + wc*64;

    for (int ot=0; ot<Mtiles; ot++){
        if (ot+1 < Mtiles){
            int bm1 = (ot+1)*64;
            uint32_t dstb = sb + S_A6 + ((ot+1)&1)*A6SZ;
            for (int e=tid; e<1536; e+=256){
                int r = e/24, ch = e - (e/24)*24;
                CP16(dstb + r*400 + ch*16, (const char*)(A + (size_t)(bm1+r)*GK) + ch*16);
            }
            asm volatile("cp.async.commit_group;" ::: "memory");
            asm volatile("cp.async.wait_group 1;" ::: "memory");
        } else {
            asm volatile("cp.async.wait_group 0;" ::: "memory");
        }
        __syncthreads();

        uint32_t aA = aBase + (ot&1)*A6SZ;
        float acc[2][4][4];
        #pragma unroll
        for (int i=0;i<2;i++)
            #pragma unroll
            for (int j=0;j<4;j++)
                #pragma unroll
                for (int r=0;r<4;r++) acc[i][j][r]=0.f;

        #pragma unroll
        for (int ks=0; ks<12; ks++){
            uint32_t Af[2][4], Bf[4][2];
            #pragma unroll
            for (int mi=0; mi<2; mi++) ldm_x4(Af[mi], aA + mi*6400 + ks*32);
            #pragma unroll
            for (int ni=0; ni<4; ni++) ldm_x2t(Bf[ni], bA + ks*4352 + ni*16);
            #pragma unroll
            for (int mi=0; mi<2; mi++)
                #pragma unroll
                for (int ni=0; ni<4; ni++)
                    mma16816f(acc[mi][ni], Af[mi][0],Af[mi][1],Af[mi][2],Af[mi][3],
                              Bf[ni][0],Bf[ni][1]);
        }

        int bm = ot*64;
        __half* O = outp + (size_t)b*sC;
        #pragma unroll
        for (int ni=0; ni<4; ni++){
            int n = bn + wc*32 + ni*8 + li4*2;
            float2 sv = *(const float2*)&Sp[n];
            #pragma unroll
            for (int mi=0; mi<2; mi++){
                int m0 = bm + wr*32 + mi*16 + gi;
                *(__half2*)(O + (size_t)m0*NPIX + n) =
                    __floats2half2_rn(acc[mi][ni][0]*sv.x, acc[mi][ni][1]*sv.y);
                *(__half2*)(O + (size_t)(m0+8)*NPIX + n) =
                    __floats2half2_rn(acc[mi][ni][2]*sv.x, acc[mi][ni][3]*sv.y);
            }
        }
        __syncthreads();
    }
}

// ---------------- depthwise 3x3, full channel image per block + inv-norm ----------------
#define DWP 144
__global__ __launch_bounds__(256)
void k_dw2(const float* __restrict__ wd){
    __shared__ __align__(16) __half img[128*DWP];
    __shared__ float wsum[8];
    int bc = blockIdx.x;
    int ch = bc % C4;
    int b  = bc / C4;
    int tid = threadIdx.x;
    const __half* in = g_qkv + (size_t)bc*NPIX;
    uint32_t sbi = su32(img);

    float w[9];
    #pragma unroll
    for (int k=0;k<9;k++) w[k] = __ldg(&wd[ch*9+k]);

    for (int r=tid; r<128; r+=256){
        *(uint4*)&img[r*DWP]       = make_uint4(0,0,0,0);
        *(uint4*)&img[r*DWP + 136] = make_uint4(0,0,0,0);
    }
    // image load via cp.async (16B per op); data col d at img[r*DWP + 8 + d]
    for (int i=tid; i<2048; i+=256){
        int r = i>>4, c = i&15;
        CP16(sbi + r*288 + 16 + c*16, (const char*)in + i*16);
    }
    asm volatile("cp.async.commit_group;" ::: "memory");
    asm volatile("cp.async.wait_group 0;" ::: "memory");
    __syncthreads();

    __half* op = g_dw + (size_t)bc*NPIX;
    float ssq = 0.f;
    #pragma unroll
    for (int it=0; it<8; it++){
        int idx = it*256 + tid;
        int r  = idx>>4;
        int x0 = (idx&15)*8;
        float acc[8] = {0.f,0.f,0.f,0.f,0.f,0.f,0.f,0.f};
        #pragma unroll
        for (int dr=-1; dr<=1; dr++){
            int rr = r + dr;
            if ((unsigned)rr < 128u){
                const __half* rp = &img[rr*DWP + x0 + 6];
                float f[12];
                #pragma unroll
                for (int j=0;j<6;j++){
                    float2 p = __half22float2(*(const __half2*)(rp + 2*j));
                    f[2*j] = p.x; f[2*j+1] = p.y;
                }
                float w0 = w[(dr+1)*3], w1 = w[(dr+1)*3+1], w2 = w[(dr+1)*3+2];
                #pragma unroll
                for (int u=0;u<8;u++)
                    acc[u] += w0*f[u+1] + w1*f[u+2] + w2*f[u+3];
            }
        }
        __align__(16) __half hv[8];
        #pragma unroll
        for (int u=0;u<8;u++){ hv[u] = __float2half(acc[u]); ssq += acc[u]*acc[u]; }
        ((uint4*)op)[idx] = *(uint4*)hv;
    }

    int slot = (ch < C) ? 0 : ((ch >= 2*C && ch < 3*C) ? 1 : -1);
    if (slot >= 0){
        #pragma unroll
        for (int o=16;o;o>>=1) ssq += __shfl_xor_sync(~0u, ssq, o);
        if ((tid&31)==0) wsum[tid>>5] = ssq;
        __syncthreads();
        if (tid==0){
            float s = 0.f;
            #pragma unroll
            for (int i=0;i<8;i++) s += wsum[i];
            float inv = 1.f/fmaxf(sqrtf(s), 1e-12f);
            if (slot==0) g_inq[b*C + ch]       = inv;
            else         g_ink[b*C + ch - 2*C] = inv;
        }
    }
}

// ---------------- q.k^T partials on tensor cores (ASEG=16) ----------------
__global__ __launch_bounds__(256)
void k_attn_mma(){
    __shared__ __half qs[48*72];
    __shared__ __half ks[48*72];
    int bh = blockIdx.x, seg = blockIdx.y;
    int b = bh>>2, hh = bh&3;
    const __half* qb = g_dw + ((size_t)b*C4 + hh*HD)*NPIX + seg*ASEGLEN;
    const __half* kb = g_dw + ((size_t)b*C4 + 2*C + hh*HD)*NPIX + seg*ASEGLEN;
    int tid = threadIdx.x, wid = tid>>5, lane = tid&31;
    uint32_t qsb = su32(qs), ksb = su32(ks);
    int n0 = wid*8;

    float acc[3][4];
    #pragma unroll
    for (int mi=0;mi<3;mi++)
        #pragma unroll
        for (int r=0;r<4;r++) acc[mi][r]=0.f;

    uint32_t aAddr = qsb + ((lane&15)*72 + (lane>>4)*8)*2;
    uint32_t bAddr = ksb + (((n0 + (lane&7))*72) + (((lane>>3)&1)*8))*2;

    for (int ck=0; ck<ASEGLEN/64; ck++){
        for (int e=tid; e<768; e+=256){
            int which = e>=384;
            int idx = e - which*384;
            int r = idx>>3, c8 = idx&7;
            const __half* src = (which? kb : qb) + (size_t)r*NPIX + ck*64 + c8*8;
            __half* dst = (which? ks : qs) + r*72 + c8*8;
            *(uint4*)dst = *(const uint4*)src;
        }
        __syncthreads();
        if (wid < 6){
            #pragma unroll
            for (int kst=0; kst<4; kst++){
                uint32_t Bf[2];
                ldm_x2(Bf, bAddr + kst*32);
                #pragma unroll
                for (int mi=0; mi<3; mi++){
                    uint32_t Af[4];
                    ldm_x4(Af, aAddr + mi*16*144 + kst*32);
                    mma16816f(acc[mi], Af[0],Af[1],Af[2],Af[3], Bf[0],Bf[1]);
                }
            }
        }
        __syncthreads();
    }
    if (wid < 6){
        int gi = lane>>2, li4 = lane&3;
        float* dst = g_spart + (size_t)(bh*ASEG+seg)*HD*HD;
        #pragma unroll
        for (int mi=0; mi<3; mi++){
            int r0 = mi*16 + gi;
            int cc = n0 + li4*2;
            dst[r0*HD+cc]     = acc[mi][0];
            dst[r0*HD+cc+1]   = acc[mi][1];
            dst[(r0+8)*HD+cc]   = acc[mi][2];
            dst[(r0+8)*HD+cc+1] = acc[mi][3];
        }
    }
}

// ---------------- combine partials, scale, softmax ----------------
__global__ void k_softmax(const float* __restrict__ temp){
    int row = blockIdx.x;
    int bh = row / HD;
    int i  = row - bh*HD;
    int b = bh >> 2, hh = bh & 3;
    int j = threadIdx.x;
    float v = -1e30f;
    if (j < HD){
        float s = 0.f;
        #pragma unroll
        for (int sg=0; sg<ASEG; sg++)
            s += g_spart[((size_t)(bh*ASEG+sg)*HD + i)*HD + j];
        v = s * __ldg(&temp[hh]) * g_inq[b*C + hh*HD + i] * g_ink[b*C + hh*HD + j];
    }
    __shared__ float sh[64];
    sh[j] = v; __syncthreads();
    for (int o=32;o>0;o>>=1){ if (j<o) sh[j]=fmaxf(sh[j],sh[j+o]); __syncthreads(); }
    float m = sh[0]; __syncthreads();
    float e = (j < HD) ? expf(v - m) : 0.f;
    sh[j] = e; __syncthreads();
    for (int o=32;o>0;o>>=1){ if (j<o) sh[j]+=sh[j+o]; __syncthreads(); }
    if (j < HD) g_attn[(size_t)bh*HD*HD + i*HD + j] = e / sh[0];
}

// ================= fused av+proj, v/gate ping-pong + weight prefetch =================
// smem layout (bytes):
//   of panel  [0 .. 52224)            192 rows x 272B
//   buf0: V0 52224, G0 65280          (A-tile ping buffer 0 = 52224, 25600B)
//   buf1: V1 78336, G1 91392          (A-tile ping buffer 1 = 78336)
//   attn      104448 .. 109824
#define S_OF2  0
#define WS_V0  52224
#define WS_G0  65280
#define WS_V1  78336
#define WS_G1  91392
#define A_OFF0 52224
#define A_OFF1 78336
#define WS_AT2 104448
#define SMEMP2 109824

__global__ __launch_bounds__(256)
void k_avproj(const __half* __restrict__ wp, float* __restrict__ outg){
    extern __shared__ __align__(16) char smem[];
    uint32_t sb = su32(smem);
    int b = blockIdx.y, pt = blockIdx.x;
    int p0 = pt*128;
    int tid = threadIdx.x, wid = tid>>5, lane = tid&31;
    int gi = lane>>2, li4 = lane&3;
    __half* of_s = (__half*)(smem + S_OF2);
    __half* at_s = (__half*)(smem + WS_AT2);

    // issue v/gate loads for head h into (vofs,gofs)
    #define ISSUE_VG(h, vofs, gofs) do { \
        const __half* vb_ = g_dw + ((size_t)b*C4 + 3*C + (h)*HD)*NPIX + p0; \
        const __half* gb_ = g_dw + ((size_t)b*C4 + C   + (h)*HD)*NPIX + p0; \
        for (int e=tid; e<1536; e+=256){ \
            int which = e>=768; \
            int idx = e - which*768; \
            int r = idx>>4, chx = idx&15; \
            const __half* src = (which? gb_ : vb_) + (size_t)r*NPIX; \
            CP16(sb + (which? (gofs) : (vofs)) + r*272 + chx*16, (const char*)src + chx*16); \
        } \
        asm volatile("cp.async.commit_group;" ::: "memory"); \
    } while(0)

    ISSUE_VG(0, WS_V0, WS_G0);

    // ---------- phase 1: of panel, heads pipelined ----------
    for (int h=0; h<HEADS; h++){
        uint32_t vcur = (h&1) ? WS_V1 : WS_V0;
        uint32_t gcur = (h&1) ? WS_G1 : WS_G0;
        if (h+1 < HEADS){
            ISSUE_VG(h+1, (h&1)? WS_V0 : WS_V1, (h&1)? WS_G0 : WS_G1);
        } else {
            // prefetch proj-weight tile 0 into A0 (buf0 region is idle during head 3)
            for (int e=tid; e<1536; e+=256){
                int r = e/24, ch = e - (e/24)*24;
                CP16(sb + A_OFF0 + r*400 + ch*16, (const char*)(wp + (size_t)r*GK) + ch*16);
            }
            asm volatile("cp.async.commit_group;" ::: "memory");
        }
        // attn -> fp16 smem (at_s free: previous head's reads done at last barrier)
        const float* ap = g_attn + (size_t)(b*HEADS+h)*HD*HD;
        for (int e=tid; e<2304; e+=256){
            int i = e/48, j = e - (e/48)*48;
            at_s[i*56+j] = __float2half(ap[e]);
        }
        asm volatile("cp.async.wait_group 1;" ::: "memory");  // head h v/g ready
        __syncthreads();

        int n0 = wid*16;
        float acc[3][2][4];
        #pragma unroll
        for (int mi=0;mi<3;mi++)
            #pragma unroll
            for (int ni=0;ni<2;ni++)
                #pragma unroll
                for (int r=0;r<4;r++) acc[mi][ni][r]=0.f;

        #pragma unroll
        for (int kst=0; kst<3; kst++){
            uint32_t Af[3][4], Bf[2][2];
            #pragma unroll
            for (int mi=0; mi<3; mi++)
                ldm_x4(Af[mi], sb + WS_AT2 + ((mi*16 + (lane&15))*56 + kst*16 + (lane>>4)*8)*2);
            #pragma unroll
            for (int ni=0; ni<2; ni++)
                ldm_x2t(Bf[ni], sb + vcur + (kst*16 + (lane&15))*272 + (n0 + ni*8)*2);
            #pragma unroll
            for (int mi=0; mi<3; mi++)
                #pragma unroll
                for (int ni=0; ni<2; ni++)
                    mma16816f(acc[mi][ni], Af[mi][0],Af[mi][1],Af[mi][2],Af[mi][3],
                              Bf[ni][0],Bf[ni][1]);
        }

        const __half* gs = (const __half*)(smem + gcur);
        #pragma unroll
        for (int mi=0; mi<3; mi++){
            #pragma unroll
            for (int ni=0; ni<2; ni++){
                int r0 = mi*16 + gi;
                int cc = n0 + ni*8 + li4*2;
                float2 g0 = __half22float2(*(const __half2*)&gs[r0*136 + cc]);
                *(__half2*)&of_s[(h*HD + r0)*136 + cc] =
                    __floats2half2_rn(acc[mi][ni][0]*sigmoidf_(g0.x),
                                      acc[mi][ni][1]*sigmoidf_(g0.y));
                float2 g1 = __half22float2(*(const __half2*)&gs[(r0+8)*136 + cc]);
                *(__half2*)&of_s[(h*HD + r0+8)*136 + cc] =
                    __floats2half2_rn(acc[mi][ni][2]*sigmoidf_(g1.x),
                                      acc[mi][ni][3]*sigmoidf_(g1.y));
            }
        }
        __syncthreads();
    }
    #undef ISSUE_VG

    // ---------- phase 2: proj GEMM, B = of panel in smem ----------
    int wr = wid>>2, wc = wid&3;
    uint32_t bA = sb + S_OF2 + (lane&15)*272 + wc*64;

    for (int ot=0; ot<3; ot++){
        if (ot+1 < 3){
            int bm1 = (ot+1)*64;
            uint32_t dstb = sb + (((ot+1)&1) ? A_OFF1 : A_OFF0);
            for (int e=tid; e<1536; e+=256){
                int r = e/24, ch = e - (e/24)*24;
                CP16(dstb + r*400 + ch*16, (const char*)(wp + (size_t)(bm1+r)*GK) + ch*16);
            }
            asm volatile("cp.async.commit_group;" ::: "memory");
            asm volatile("cp.async.wait_group 1;" ::: "memory");
        } else {
            asm volatile("cp.async.wait_group 0;" ::: "memory");
        }
        __syncthreads();

        uint32_t aA = sb + ((ot&1) ? A_OFF1 : A_OFF0)
                    + ((wr*32 + (lane&15))*400) + (lane>>4)*16;
        float acc[2][4][4];
        #pragma unroll
        for (int i=0;i<2;i++)
            #pragma unroll
            for (int j=0;j<4;j++)
                #pragma unroll
                for (int r=0;r<4;r++) acc[i][j][r]=0.f;

        #pragma unroll
        for (int ks=0; ks<12; ks++){
            uint32_t Af[2][4], Bf[4][2];
            #pragma unroll
            for (int mi=0; mi<2; mi++) ldm_x4(Af[mi], aA + mi*6400 + ks*32);
            #pragma unroll
            for (int ni=0; ni<4; ni++) ldm_x2t(Bf[ni], bA + ks*4352 + ni*16);
            #pragma unroll
            for (int mi=0; mi<2; mi++)
                #pragma unroll
                for (int ni=0; ni<4; ni++)
                    mma16816f(acc[mi][ni], Af[mi][0],Af[mi][1],Af[mi][2],Af[mi][3],
                              Bf[ni][0],Bf[ni][1]);
        }

        int bm = ot*64;
        float* O = outg + (size_t)b*C*NPIX + p0;
        #pragma unroll
        for (int ni=0; ni<4; ni++){
            int n = wc*32 + ni*8 + li4*2;
            #pragma unroll
            for (int mi=0; mi<2; mi++){
                int m0 = bm + wr*32 + mi*16 + gi;
                *(float2*)(O + (size_t)m0*NPIX + n) =
                    make_float2(acc[mi][ni][0], acc[mi][ni][1]);
                *(float2*)(O + (size_t)(m0+8)*NPIX + n) =
                    make_float2(acc[mi][ni][2], acc[mi][ni][3]);
            }
        }
        __syncthreads();
    }
}

// ---------------- host ----------------
extern "C" void kernel_launch(void* const* d_in, const int* in_sizes, int n_in,
                              void* d_out, int out_size){
    const float* x      = (const float*)d_in[0];
    const float* w_fc1  = (const float*)d_in[1];
    const float* w_fc2  = (const float*)d_in[2];
    const float* w_sp   = (const float*)d_in[3];
    const float* w_qkv  = (const float*)d_in[4];
    const float* w_dw   = (const float*)d_in[5];
    const float* w_proj = (const float*)d_in[6];
    const float* temp   = (const float*)d_in[7];
    float* out = (float*)d_out;

    __half *wq, *wp, *qkv;
    float *sg;
    cudaGetSymbolAddress((void**)&wq,  g_wq);
    cudaGetSymbolAddress((void**)&wp,  g_wp);
    cudaGetSymbolAddress((void**)&qkv, g_qkv);
    cudaGetSymbolAddress((void**)&sg,  g_sg);

    cudaFuncSetAttribute(k_hmma6,  cudaFuncAttributeMaxDynamicSharedMemorySize, SMEM6);
    cudaFuncSetAttribute(k_avproj, cudaFuncAttributeMaxDynamicSharedMemorySize, SMEMP2);

    k_stats        <<<dim3(NTILE, NB), 256>>>(x);
    k_chan_gate    <<<NB, 192>>>(w_fc1, w_fc2);
    k_spatial_conv <<<NB*NPIX/256, 256>>>(w_sp);

    k_wcvt2<<<((WQ_ELEMS + WP_ELEMS)/4 + 255)/256, 256>>>(w_qkv, w_proj, wq, wp);

    // qkv = sg(p) * ((w_qkv*cg) @ x): fp32-B converted at staging, half out
    k_hmma6<<<NB*(NPIX/128), 256, SMEM6>>>(
        wq, (long)C4*GK, x, qkv, (long)C4*NPIX, sg, C4, 12);

    k_dw2<<<NB*C4, 256>>>(w_dw);     // dw + inverse norms

    k_attn_mma<<<dim3(NB*HEADS, ASEG), 256>>>();
    k_softmax  <<<NB*HEADS*HD, 64>>>(temp);

    // fused (attn@v)*sigmoid(gate) + projection -> d_out (pipelined)
    k_avproj<<<dim3(NPIX/128, NB), 256, SMEMP2>>>(wp, out);
}